// round 5
// baseline (speedup 1.0000x reference)
#include <cuda_runtime.h>

#define NMAX   100000
#define EMAX   1600000
#define INH    18
#define OUTH   11
#define OUTP   12      // padded to 3x float4
#define NCLASS 40
#define CDIM   51      // NCLASS + OUTH
#define NBLK_SCAN 128  // >= ceil(NMAX/1024) = 98

// ---------------- scratch (device globals; no allocs allowed) ----------------
__device__ int   g_cnt   [NMAX];       // in-degree (edges only)
__device__ int   g_rowptr[NMAX];       // CSR row start
__device__ int   g_cur   [NMAX];       // scatter cursor
__device__ int   g_blksum[NBLK_SCAN];
__device__ int   g_blkoff[NBLK_SCAN];
__device__ float g_dinv[NMAX];
__device__ float g_sdin[NMAX];
__device__ __align__(16) float g_M  [NMAX * OUTP];
__device__ __align__(16) float g_Y1 [NMAX * OUTP];
__device__ __align__(16) float g_Y2 [NMAX * OUTP];
__device__ int   g_esrc[EMAX];         // CSR: src per slot
__device__ float g_enrm[EMAX];         // CSR: dinv[s]*dinv[d] per slot
__device__ float g_W12[INH * OUTH];    // W1 @ W2  [18,11]
__device__ float g_c  [OUTH];          // b1 @ W2  [11]

// ---------------- kernels ----------------

__global__ void k_init(int n) {
    int i = blockIdx.x * blockDim.x + threadIdx.x;
    if (i < n) g_cnt[i] = 0;
}

// W12 = W1 @ W2 ([18,nh]@[nh,11]); c = b1 @ W2. One block.
__global__ void k_w12(const float* __restrict__ W1, const float* __restrict__ W2,
                      const float* __restrict__ b1, int nh) {
    int t = threadIdx.x;
    if (t < INH * OUTH) {
        int i = t / OUTH, j = t % OUTH;
        float s = 0.f;
        for (int k = 0; k < nh; k++) s += W1[i * nh + k] * W2[k * OUTH + j];
        g_W12[t] = s;
    } else if (t < INH * OUTH + OUTH) {
        int j = t - INH * OUTH;
        float s = 0.f;
        for (int k = 0; k < nh; k++) s += b1[k] * W2[k * OUTH + j];
        g_c[j] = s;
    }
}

// in-degree histogram (int), 4 edges per thread via int4
__global__ void k_deg(const int* __restrict__ dst, int e) {
    int i = blockIdx.x * blockDim.x + threadIdx.x;
    int base = i * 4;
    if (base + 3 < e) {
        int4 d4 = *reinterpret_cast<const int4*>(dst + base);
        atomicAdd(&g_cnt[d4.x], 1);
        atomicAdd(&g_cnt[d4.y], 1);
        atomicAdd(&g_cnt[d4.z], 1);
        atomicAdd(&g_cnt[d4.w], 1);
    } else {
        for (int k = base; k < e; k++) atomicAdd(&g_cnt[dst[k]], 1);
    }
}

// ---- exclusive scan of g_cnt into g_rowptr (1024 elems per block) ----
__global__ void k_scan1(int n) {
    __shared__ int sh[256];
    int b = blockIdx.x, t = threadIdx.x;
    int base = b * 1024 + t * 4;
    int v0 = 0, v1 = 0, v2 = 0, v3 = 0;
    if (base + 3 < n) {
        int4 c = *reinterpret_cast<const int4*>(&g_cnt[base]);
        v0 = c.x; v1 = c.y; v2 = c.z; v3 = c.w;
    } else {
        if (base     < n) v0 = g_cnt[base];
        if (base + 1 < n) v1 = g_cnt[base + 1];
        if (base + 2 < n) v2 = g_cnt[base + 2];
        if (base + 3 < n) v3 = g_cnt[base + 3];
    }
    int tsum = v0 + v1 + v2 + v3;
    sh[t] = tsum;
    __syncthreads();
    for (int off = 1; off < 256; off <<= 1) {
        int x = (t >= off) ? sh[t - off] : 0;
        __syncthreads();
        sh[t] += x;
        __syncthreads();
    }
    int excl = sh[t] - tsum;
    if (t == 255) g_blksum[b] = sh[255];
    if (base     < n) g_rowptr[base]     = excl;
    if (base + 1 < n) g_rowptr[base + 1] = excl + v0;
    if (base + 2 < n) g_rowptr[base + 2] = excl + v0 + v1;
    if (base + 3 < n) g_rowptr[base + 3] = excl + v0 + v1 + v2;
}

__global__ void k_scan2(int nblk) {
    __shared__ int sh[NBLK_SCAN];
    int t = threadIdx.x;
    int v = (t < nblk) ? g_blksum[t] : 0;
    sh[t] = v;
    __syncthreads();
    for (int off = 1; off < NBLK_SCAN; off <<= 1) {
        int x = (t >= off) ? sh[t - off] : 0;
        __syncthreads();
        sh[t] += x;
        __syncthreads();
    }
    g_blkoff[t] = sh[t] - v;   // exclusive
}

__global__ void k_scan3(int n) {
    int b = blockIdx.x;
    int off = g_blkoff[b];
    int base = b * 1024 + threadIdx.x * 4;
#pragma unroll
    for (int q = 0; q < 4; q++) {
        int idx = base + q;
        if (idx < n) {
            int r = g_rowptr[idx] + off;
            g_rowptr[idx] = r;
            g_cur[idx]    = r;
        }
    }
}

// dinv = rsqrt(cnt+1); M = x @ W12; Y1 = di^2 * M (self-loop term)
__global__ void k_dinvM(const float* __restrict__ x, int n) {
    __shared__ float w[INH * OUTH];
    for (int t = threadIdx.x; t < INH * OUTH; t += blockDim.x) w[t] = g_W12[t];
    __syncthreads();
    int i = blockIdx.x * blockDim.x + threadIdx.x;
    if (i >= n) return;
    float di = rsqrtf((float)(g_cnt[i] + 1));
    g_dinv[i] = di;
    float di2 = di * di;
    float xr[INH];
#pragma unroll
    for (int k = 0; k < INH; k++) xr[k] = x[i * INH + k];
    float o[OUTP];
#pragma unroll
    for (int j = 0; j < OUTH; j++) {
        float s = 0.f;
#pragma unroll
        for (int k = 0; k < INH; k++) s += xr[k] * w[k * OUTH + j];
        o[j] = s;
    }
    o[OUTH] = 0.f;
    float4* mp = reinterpret_cast<float4*>(&g_M[i * OUTP]);
    float4* yp = reinterpret_cast<float4*>(&g_Y1[i * OUTP]);
#pragma unroll
    for (int q = 0; q < 3; q++) {
        float4 v = make_float4(o[q*4], o[q*4+1], o[q*4+2], o[q*4+3]);
        mp[q] = v;
        yp[q] = make_float4(v.x * di2, v.y * di2, v.z * di2, v.w * di2);
    }
}

// scatter edges into CSR slots (counting sort by dst)
__global__ void k_scatter(const int* __restrict__ ei, int e) {
    int i = blockIdx.x * blockDim.x + threadIdx.x;
    if (i >= e) return;
    int s = ei[i];
    int d = ei[e + i];
    int pos = atomicAdd(&g_cur[d], 1);
    g_esrc[pos] = s;
    g_enrm[pos] = g_dinv[s] * g_dinv[d];
}

// pass 0 (dst-major, gather-only): Y1[i] = self + sum nrm*M[src];
// Y2[i] = di^2*Y1[i]; sdin[i] = (sum nrm)/di  (lane 12, from broadcast nrm)
__global__ void k_agg0(int n) {
    int tid  = blockIdx.x * blockDim.x + threadIdx.x;
    int node = tid >> 4;
    int lane = tid & 15;
    if (node >= n) return;
    int beg = g_rowptr[node];
    int cnt = g_cnt[node];
    float acc = 0.f;
#pragma unroll 4
    for (int k = 0; k < cnt; k++) {
        int   s   = __ldg(&g_esrc[beg + k]);
        float nrm = __ldg(&g_enrm[beg + k]);
        if (lane < 12) acc += nrm * g_M[s * OUTP + lane];
        else           acc += nrm;     // lanes 12-15: sum of nrm
    }
    float di = g_dinv[node];
    if (lane < 12) {
        float y1 = g_Y1[node * OUTP + lane] + acc;   // self term preloaded
        g_Y1[node * OUTP + lane] = y1;
        g_Y2[node * OUTP + lane] = di * di * y1;
    } else if (lane == 12) {
        g_sdin[node] = acc / di;       // sum dinv[src] = (sum nrm)/dinv[d]
    }
}

// pass 1: Y2[i] += sum nrm*Y1[src]
__global__ void k_agg1(int n) {
    int tid  = blockIdx.x * blockDim.x + threadIdx.x;
    int node = tid >> 4;
    int lane = tid & 15;
    if (node >= n || lane >= 12) return;
    int beg = g_rowptr[node];
    int cnt = g_cnt[node];
    float acc = 0.f;
#pragma unroll 4
    for (int k = 0; k < cnt; k++) {
        int   s   = __ldg(&g_esrc[beg + k]);
        float nrm = __ldg(&g_enrm[beg + k]);
        acc += nrm * g_Y1[s * OUTP + lane];
    }
    g_Y2[node * OUTP + lane] += acc;   // self term preloaded by agg0
}

// epilogue: emb_b = relu(Y2 + s*c + b2);  out = [emb_a, emb_b] @ Wc + bc
__global__ void k_final(const float* __restrict__ emb_a, const float* __restrict__ b2,
                        const float* __restrict__ Wc, const float* __restrict__ bc,
                        float* __restrict__ out, int n) {
    __shared__ float wsm[CDIM * NCLASS];
    __shared__ float bsm[NCLASS];
    __shared__ float csm[OUTH];
    __shared__ float b2sm[OUTH];
    for (int t = threadIdx.x; t < CDIM * NCLASS; t += blockDim.x) wsm[t] = Wc[t];
    if (threadIdx.x < NCLASS) bsm[threadIdx.x] = bc[threadIdx.x];
    if (threadIdx.x < OUTH) { csm[threadIdx.x] = g_c[threadIdx.x]; b2sm[threadIdx.x] = b2[threadIdx.x]; }
    __syncthreads();
    int i = blockIdx.x * blockDim.x + threadIdx.x;
    if (i >= n) return;

    float acc[NCLASS];
#pragma unroll
    for (int k = 0; k < NCLASS; k++) acc[k] = bsm[k];

    const float4* ea = reinterpret_cast<const float4*>(&emb_a[(size_t)i * NCLASS]);
#pragma unroll
    for (int m4 = 0; m4 < NCLASS / 4; m4++) {
        float4 v = ea[m4];
        float vv[4] = {v.x, v.y, v.z, v.w};
#pragma unroll
        for (int q = 0; q < 4; q++) {
            float a = vv[q];
            int m = m4 * 4 + q;
#pragma unroll
            for (int k = 0; k < NCLASS; k++) acc[k] += a * wsm[m * NCLASS + k];
        }
    }

    float di = g_dinv[i];
    float s = di * (di + g_sdin[i]);
#pragma unroll
    for (int j = 0; j < OUTH; j++) {
        float h = g_Y2[(size_t)i * OUTP + j] + s * csm[j] + b2sm[j];
        h = fmaxf(h, 0.0f);
#pragma unroll
        for (int k = 0; k < NCLASS; k++) acc[k] += h * wsm[(NCLASS + j) * NCLASS + k];
    }

    float4* op = reinterpret_cast<float4*>(&out[(size_t)i * NCLASS]);
#pragma unroll
    for (int q = 0; q < NCLASS / 4; q++)
        op[q] = make_float4(acc[q * 4], acc[q * 4 + 1], acc[q * 4 + 2], acc[q * 4 + 3]);
}

// ---------------- launch ----------------
extern "C" void kernel_launch(void* const* d_in, const int* in_sizes, int n_in,
                              void* d_out, int out_size) {
    const float* x     = (const float*)d_in[0];
    const int*   ei    = (const int*)d_in[1];     // int32 (JAX x64 disabled)
    const float* emb_a = (const float*)d_in[2];
    const float* W1    = (const float*)d_in[3];
    const float* b1    = (const float*)d_in[4];
    const float* W2    = (const float*)d_in[5];
    const float* b2    = (const float*)d_in[6];
    const float* Wc    = (const float*)d_in[7];
    const float* bc    = (const float*)d_in[8];
    float* out = (float*)d_out;

    int n  = in_sizes[0] / INH;   // 100000
    int e  = in_sizes[1] / 2;     // 1600000
    int nh = in_sizes[4];         // 256 (b1 length)

    const int TB = 256;
    int nblk = (n + 1023) / 1024;             // scan blocks (98)
    k_init   <<<(n + TB - 1) / TB, TB>>>(n);
    k_w12    <<<1, 256>>>(W1, W2, b1, nh);
    k_deg    <<<(e / 4 + TB - 1) / TB, TB>>>(ei + e, e);
    k_scan1  <<<nblk, 256>>>(n);
    k_scan2  <<<1, NBLK_SCAN>>>(nblk);
    k_scan3  <<<nblk, 256>>>(n);
    k_dinvM  <<<(n + TB - 1) / TB, TB>>>(x, n);
    k_scatter<<<(e + TB - 1) / TB, TB>>>(ei, e);
    k_agg0   <<<(n * 16 + TB - 1) / TB, TB>>>(n);
    k_agg1   <<<(n * 16 + TB - 1) / TB, TB>>>(n);
    k_final  <<<(n + TB - 1) / TB, TB>>>(emb_a, b2, Wc, bc, out, n);
}